// round 3
// baseline (speedup 1.0000x reference)
#include <cuda_runtime.h>

// Problem constants (fixed shapes from reference)
constexpr int B_   = 2;
constexpr int C_   = 64;
constexpr int CQK_ = 8;
constexpr int N_   = 4096;   // 16*16*16

constexpr int KS  = 8;    // key-dim split factor (partials are addable: no max subtraction)
constexpr int TQ  = 128;  // queries per block (thread per query)
constexpr int TK  = 128;  // key tile staged in smem

// -------- scratch (static device arrays; no allocation allowed) --------
__device__ float  g_q[B_ * N_ * CQK_];          // [B][N][8]
__device__ float  g_k[B_ * N_ * CQK_];          // [B][N][8]
__device__ float  g_v[B_ * N_ * C_];            // [B][N][64]
__device__ float2 g_pacc[B_ * KS * 32 * N_];    // [B][KS][32 ch-pairs][N]
__device__ float  g_pden[B_ * KS * N_];         // [B][KS][N]

// -------- packed f32x2 helpers (full-rate FMA on Blackwell) --------
__device__ __forceinline__ unsigned long long fma2(unsigned long long a,
                                                   unsigned long long b,
                                                   unsigned long long c) {
    unsigned long long d;
    asm("fma.rn.f32x2 %0, %1, %2, %3;" : "=l"(d) : "l"(a), "l"(b), "l"(c));
    return d;
}
__device__ __forceinline__ unsigned long long mul2(unsigned long long a,
                                                   unsigned long long b) {
    unsigned long long d;
    asm("mul.rn.f32x2 %0, %1, %2;" : "=l"(d) : "l"(a), "l"(b));
    return d;
}
__device__ __forceinline__ unsigned long long pack2(float lo, float hi) {
    unsigned long long r;
    asm("mov.b64 %0, {%1, %2};" : "=l"(r) : "f"(lo), "f"(hi));
    return r;
}
__device__ __forceinline__ float hadd2(unsigned long long a) {
    float lo, hi;
    asm("mov.b64 {%0, %1}, %2;" : "=f"(lo), "=f"(hi) : "l"(a));
    return lo + hi;
}

// ============================================================================
// Kernel 1: QKV projection (1x1x1 convs == per-position linear over channels)
// One thread per position. x layout [B][C][N] -> coalesced per-channel loads.
// ============================================================================
__global__ __launch_bounds__(128) void qkv_kernel(
    const float* __restrict__ x,
    const float* __restrict__ Wq, const float* __restrict__ bq,
    const float* __restrict__ Wk, const float* __restrict__ bk,
    const float* __restrict__ Wv, const float* __restrict__ bv)
{
    __shared__ float swq[CQK_ * C_], swk[CQK_ * C_], swv[C_ * C_];
    __shared__ float sbq[CQK_], sbk[CQK_], sbv[C_];
    const int tid = threadIdx.x;
    for (int i = tid; i < CQK_ * C_; i += blockDim.x) { swq[i] = Wq[i]; swk[i] = Wk[i]; }
    for (int i = tid; i < C_ * C_;  i += blockDim.x) { swv[i] = Wv[i]; }
    if (tid < CQK_) { sbq[tid] = bq[tid]; sbk[tid] = bk[tid]; }
    if (tid < C_)   { sbv[tid] = bv[tid]; }
    __syncthreads();

    const int pos = blockIdx.x * blockDim.x + tid;   // 0..B*N-1, pos == b*N + n
    const int b = pos >> 12;
    const int n = pos & (N_ - 1);

    float xr[C_];
    const float* xb = x + (size_t)b * C_ * N_ + n;
#pragma unroll
    for (int c = 0; c < C_; c++) xr[c] = xb[c * N_];

    // q, k (8 channels each)
    float qv[CQK_], kv[CQK_];
#pragma unroll
    for (int j = 0; j < CQK_; j++) {
        float aq = sbq[j], ak = sbk[j];
#pragma unroll
        for (int c = 0; c < C_; c++) {
            aq += swq[j * C_ + c] * xr[c];
            ak += swk[j * C_ + c] * xr[c];
        }
        qv[j] = aq; kv[j] = ak;
    }
    float4* qo = (float4*)(g_q + (size_t)pos * CQK_);
    float4* ko = (float4*)(g_k + (size_t)pos * CQK_);
    qo[0] = make_float4(qv[0], qv[1], qv[2], qv[3]);
    qo[1] = make_float4(qv[4], qv[5], qv[6], qv[7]);
    ko[0] = make_float4(kv[0], kv[1], kv[2], kv[3]);
    ko[1] = make_float4(kv[4], kv[5], kv[6], kv[7]);

    // v (64 channels, in chunks of 8 to bound registers)
    float* vo = g_v + (size_t)pos * C_;
#pragma unroll
    for (int c0 = 0; c0 < C_; c0 += 8) {
        float acc[8];
#pragma unroll
        for (int j = 0; j < 8; j++) acc[j] = sbv[c0 + j];
#pragma unroll
        for (int c = 0; c < C_; c++) {
            float xv = xr[c];
#pragma unroll
            for (int j = 0; j < 8; j++) acc[j] += swv[(c0 + j) * C_ + c] * xv;
        }
        ((float4*)(vo + c0))[0] = make_float4(acc[0], acc[1], acc[2], acc[3]);
        ((float4*)(vo + c0))[1] = make_float4(acc[4], acc[5], acc[6], acc[7]);
    }
}

// ============================================================================
// Kernel 2: flash-style attention, split over keys (KS partitions).
// Block: TQ threads, one query per thread. Key tile staged in smem; all lanes
// read the same key row -> pure broadcast LDS (conflict-free).
// No max subtraction (energy range safe in fp32) => partials add linearly.
// ============================================================================
__global__ __launch_bounds__(TQ) void attn_kernel()
{
    __shared__ float4     sk[TK * 2];    // [TK][8]  keys, 4 KB
    __shared__ ulonglong2 sv[TK * 16];   // [TK][64] values as f32x2 pairs, 32 KB

    const int b  = blockIdx.z;
    const int ks = blockIdx.y;
    const int nq = blockIdx.x * TQ + threadIdx.x;

    // load this thread's query (8 floats) into packed f32x2 regs
    const float4* qp = (const float4*)(g_q + ((size_t)b * N_ + nq) * CQK_);
    const float4 q0 = qp[0], q1 = qp[1];
    const unsigned long long qq[4] = {
        pack2(q0.x, q0.y), pack2(q0.z, q0.w),
        pack2(q1.x, q1.y), pack2(q1.z, q1.w)
    };

    unsigned long long acc[32];
#pragma unroll
    for (int i = 0; i < 32; i++) acc[i] = 0ull;
    float den = 0.0f;

    const int kbase = ks * (N_ / KS);  // 512 keys per split
    for (int kt = 0; kt < N_ / KS; kt += TK) {
        // stage tiles (coalesced 16B loads)
        const float4* kg = (const float4*)(g_k + ((size_t)b * N_ + kbase + kt) * CQK_);
        for (int i = threadIdx.x; i < TK * 2; i += TQ) sk[i] = kg[i];
        const ulonglong2* vg = (const ulonglong2*)(g_v + ((size_t)b * N_ + kbase + kt) * C_);
        for (int i = threadIdx.x; i < TK * 16; i += TQ) sv[i] = vg[i];
        __syncthreads();

#pragma unroll 2
        for (int m = 0; m < TK; m++) {
            const float4 ka = sk[2 * m], kb = sk[2 * m + 1];
            unsigned long long e2 = mul2(qq[3], pack2(kb.z, kb.w));
            e2 = fma2(qq[2], pack2(kb.x, kb.y), e2);
            e2 = fma2(qq[1], pack2(ka.z, ka.w), e2);
            e2 = fma2(qq[0], pack2(ka.x, ka.y), e2);
            const float p = __expf(hadd2(e2));
            den += p;
            const unsigned long long pp = pack2(p, p);

            const ulonglong2* vr = sv + m * 16;
#pragma unroll
            for (int j = 0; j < 16; j++) {
                const ulonglong2 vv = vr[j];
                acc[2 * j]     = fma2(vv.x, pp, acc[2 * j]);
                acc[2 * j + 1] = fma2(vv.y, pp, acc[2 * j + 1]);
            }
        }
        __syncthreads();
    }

    // write partials: layout [B][KS][32 pairs][N] -> coalesced across threads
    const size_t base = ((size_t)(b * KS + ks) * 32) * N_ + nq;
#pragma unroll
    for (int i = 0; i < 32; i++) {
        float lo, hi;
        asm("mov.b64 {%0, %1}, %2;" : "=f"(lo), "=f"(hi) : "l"(acc[i]));
        g_pacc[base + (size_t)i * N_] = make_float2(lo, hi);
    }
    g_pden[(size_t)(b * KS + ks) * N_ + nq] = den;
}

// ============================================================================
// Kernel 3: combine split-K partials + residual.
// Thread t owns one (pos = b*N+n, channel-pair-group g of 8 pairs).
// All g_pacc / g_pden / x / out accesses are coalesced across threadIdx.x.
// ============================================================================
__global__ __launch_bounds__(256) void combine_kernel(
    const float* __restrict__ x,
    const float* __restrict__ gamma,
    float* __restrict__ out)
{
    const int t   = blockIdx.x * blockDim.x + threadIdx.x;  // 0 .. 4*B*N-1
    const int pos = t & (B_ * N_ - 1);                      // b*N + n
    const int g   = t >> 13;                                // channel-pair group 0..3
    const int b = pos >> 12;
    const int n = pos & (N_ - 1);

    float den = 0.0f;
#pragma unroll
    for (int s = 0; s < KS; s++) den += g_pden[(size_t)(b * KS + s) * N_ + n];
    const float scale = gamma[0] / den;

#pragma unroll
    for (int i = g * 8; i < g * 8 + 8; i++) {
        float ax = 0.0f, ay = 0.0f;
#pragma unroll
        for (int s = 0; s < KS; s++) {
            const float2 p = g_pacc[((size_t)(b * KS + s) * 32 + i) * N_ + n];
            ax += p.x; ay += p.y;
        }
        const int c = 2 * i;
        const size_t o0 = ((size_t)b * C_ + c) * N_ + n;
        const size_t o1 = o0 + N_;
        out[o0] = fmaf(scale, ax, x[o0]);
        out[o1] = fmaf(scale, ay, x[o1]);
    }
}

// ============================================================================
extern "C" void kernel_launch(void* const* d_in, const int* in_sizes, int n_in,
                              void* d_out, int out_size)
{
    const float* x     = (const float*)d_in[0];
    const float* Wq    = (const float*)d_in[1];
    const float* bq    = (const float*)d_in[2];
    const float* Wk    = (const float*)d_in[3];
    const float* bk    = (const float*)d_in[4];
    const float* Wv    = (const float*)d_in[5];
    const float* bv    = (const float*)d_in[6];
    const float* gamma = (const float*)d_in[7];
    float* out = (float*)d_out;

    qkv_kernel<<<(B_ * N_) / 128, 128>>>(x, Wq, bq, Wk, bk, Wv, bv);
    attn_kernel<<<dim3(N_ / TQ, KS, B_), TQ>>>();
    combine_kernel<<<(4 * B_ * N_) / 256, 256>>>(x, gamma, out);
}

// round 5
// speedup vs baseline: 2.2580x; 2.2580x over previous
#include <cuda_runtime.h>
#include <cstdint>

// Shapes (fixed)
constexpr int B_   = 2;
constexpr int C_   = 64;
constexpr int CQK_ = 8;
constexpr int N_   = 4096;

constexpr int KS2 = 2;     // key splits
constexpr int MT  = 64;    // queries per CTA (4 warps x m16)
constexpr int NK  = 128;   // keys staged per tile
constexpr int VSTRIDE = 72;  // padded floats per key row in smem (bank-conflict-free)

// ---------------- scratch ----------------
__device__ float g_q[B_ * N_ * CQK_];          // [B][N][8]
__device__ float g_k[B_ * N_ * CQK_];          // [B][N][8]
__device__ float g_v[B_ * N_ * C_];            // [B][N][64] key-major, tf32-rounded
__device__ float g_pacc[B_ * KS2 * N_ * C_];   // [B][S][q][64]
__device__ float g_pden[B_ * KS2 * N_];        // [B][S][q]

// ---------------- helpers ----------------
__device__ __forceinline__ unsigned long long fma2(unsigned long long a, unsigned long long b, unsigned long long c) {
    unsigned long long d;
    asm("fma.rn.f32x2 %0, %1, %2, %3;" : "=l"(d) : "l"(a), "l"(b), "l"(c));
    return d;
}
__device__ __forceinline__ unsigned long long mul2(unsigned long long a, unsigned long long b) {
    unsigned long long d;
    asm("mul.rn.f32x2 %0, %1, %2;" : "=l"(d) : "l"(a), "l"(b));
    return d;
}
__device__ __forceinline__ unsigned long long pack2(float lo, float hi) {
    unsigned long long r;
    asm("mov.b64 %0, {%1, %2};" : "=l"(r) : "f"(lo), "f"(hi));
    return r;
}
__device__ __forceinline__ float hadd2(unsigned long long a) {
    float lo, hi;
    asm("mov.b64 {%0, %1}, %2;" : "=f"(lo), "=f"(hi) : "l"(a));
    return lo + hi;
}
__device__ __forceinline__ uint32_t f2tf32(float f) {
    uint32_t r;
    asm("cvt.rna.tf32.f32 %0, %1;" : "=r"(r) : "f"(f));
    return r;
}
// D[16x8] += A[16x8, tf32 row] * B[8x8, tf32 col]; accumulate in place
__device__ __forceinline__ void mma_tf32(float* d, const uint32_t* a, uint32_t b0, uint32_t b1) {
    asm volatile(
        "mma.sync.aligned.m16n8k8.row.col.f32.tf32.tf32.f32 "
        "{%0,%1,%2,%3}, {%4,%5,%6,%7}, {%8,%9}, {%0,%1,%2,%3};"
        : "+f"(d[0]), "+f"(d[1]), "+f"(d[2]), "+f"(d[3])
        : "r"(a[0]), "r"(a[1]), "r"(a[2]), "r"(a[3]), "r"(b0), "r"(b1));
}

// ============================================================================
// Kernel 1: QKV projection. 256 blocks x 128 threads; warp w covers a channel
// quarter for 32 positions. V stored key-major [B][N][64], tf32-rounded.
// ============================================================================
__global__ __launch_bounds__(128) void qkv_kernel(
    const float* __restrict__ x,
    const float* __restrict__ Wq, const float* __restrict__ bq,
    const float* __restrict__ Wk, const float* __restrict__ bk,
    const float* __restrict__ Wv, const float* __restrict__ bv)
{
    __shared__ float swq[CQK_ * C_], swk[CQK_ * C_], swv[C_ * C_];
    __shared__ float sbq[CQK_], sbk[CQK_], sbv[C_];
    const int tid = threadIdx.x, wid = tid >> 5, lid = tid & 31;
    for (int i = tid; i < CQK_ * C_; i += 128) { swq[i] = Wq[i]; swk[i] = Wk[i]; }
    for (int i = tid; i < C_ * C_;  i += 128) { swv[i] = Wv[i]; }
    if (tid < CQK_) { sbq[tid] = bq[tid]; sbk[tid] = bk[tid]; }
    if (tid < C_)   { sbv[tid] = bv[tid]; }
    __syncthreads();

    const int pos = blockIdx.x * 32 + lid;     // b*N + n
    const int b = pos >> 12;
    const int n = pos & (N_ - 1);

    float xr[C_];
    const float* xb = x + (size_t)b * C_ * N_ + n;
#pragma unroll
    for (int c = 0; c < C_; c++) xr[c] = xb[(size_t)c * N_];

    if (wid < 2) {
        const float* W  = wid ? swk : swq;
        const float* bb = wid ? sbk : sbq;
        float o[CQK_];
#pragma unroll
        for (int j = 0; j < CQK_; j++) {
            float a = bb[j];
#pragma unroll
            for (int c = 0; c < C_; c++) a += W[j * C_ + c] * xr[c];
            o[j] = a;
        }
        float* dst = (wid ? g_k : g_q) + (size_t)pos * CQK_;
        ((float4*)dst)[0] = make_float4(o[0], o[1], o[2], o[3]);
        ((float4*)dst)[1] = make_float4(o[4], o[5], o[6], o[7]);
    }

    const int vstart[4] = {0, 12, 24, 44};
    const int vcnt[4]   = {12, 12, 20, 20};
    const int c0 = vstart[wid], cnt = vcnt[wid];
    float* vo = g_v + (size_t)pos * C_;
    for (int jj = 0; jj < cnt; jj += 4) {
        float a0 = sbv[c0 + jj], a1 = sbv[c0 + jj + 1], a2 = sbv[c0 + jj + 2], a3 = sbv[c0 + jj + 3];
#pragma unroll
        for (int c = 0; c < C_; c++) {
            const float xv = xr[c];
            a0 += swv[(c0 + jj)     * C_ + c] * xv;
            a1 += swv[(c0 + jj + 1) * C_ + c] * xv;
            a2 += swv[(c0 + jj + 2) * C_ + c] * xv;
            a3 += swv[(c0 + jj + 3) * C_ + c] * xv;
        }
        *(float4*)(vo + c0 + jj) = make_float4(
            __uint_as_float(f2tf32(a0)), __uint_as_float(f2tf32(a1)),
            __uint_as_float(f2tf32(a2)), __uint_as_float(f2tf32(a3)));
    }
}

// ============================================================================
// Kernel 2: flash attention, PV on mma.sync tf32 (m16n8k8).
// Grid (N/MT, KS2, B), 128 threads = 4 warps; warp w owns queries [16w,16w+16).
// Per NK=128 key tile: scalar QK^T+exp straight into A fragments, V (tf32)
// staged [key][72] in smem as the col-major B operand, 8 n-tiles of mma.
// ============================================================================
__global__ __launch_bounds__(128) void attn_mma_kernel()
{
    __shared__ float4 skt[NK * 2];                // K tile [128 keys][8]
    __shared__ float  svt[NK * VSTRIDE];          // V tile [128 keys][72 pad]

    const int tid = threadIdx.x, wid = tid >> 5, lane = tid & 31;
    const int b = blockIdx.z, sp = blockIdx.y, qt = blockIdx.x;
    const int grp = lane >> 2;        // 0..7 : fragment row group / n col
    const int cq  = lane & 3;         // 0..3 : key class / col pair

    const int q0g = qt * MT + wid * 16 + grp;     // global q row (r0)
    const int q1g = q0g + 8;                      // r1

    // queries for rows r0, r1 (8 floats each) packed for fma2
    const float4* qp0 = (const float4*)(g_q + ((size_t)b * N_ + q0g) * CQK_);
    const float4* qp1 = (const float4*)(g_q + ((size_t)b * N_ + q1g) * CQK_);
    const float4 qa0 = qp0[0], qa1 = qp0[1], qb0 = qp1[0], qb1 = qp1[1];
    const unsigned long long qq0[4] = { pack2(qa0.x, qa0.y), pack2(qa0.z, qa0.w),
                                        pack2(qa1.x, qa1.y), pack2(qa1.z, qa1.w) };
    const unsigned long long qq1[4] = { pack2(qb0.x, qb0.y), pack2(qb0.z, qb0.w),
                                        pack2(qb1.x, qb1.y), pack2(qb1.z, qb1.w) };

    float d[8][4];
#pragma unroll
    for (int j = 0; j < 8; j++) { d[j][0] = d[j][1] = d[j][2] = d[j][3] = 0.0f; }
    float den0 = 0.0f, den1 = 0.0f;

    const int kbase0 = sp * (N_ / KS2);
    for (int t = 0; t < (N_ / KS2) / NK; t++) {
        const int kstart = kbase0 + t * NK;
        __syncthreads();
        // stage K: 256 float4
        const float4* kg = (const float4*)(g_k + ((size_t)b * N_ + kstart) * CQK_);
        skt[tid] = kg[tid];
        skt[tid + 128] = kg[tid + 128];
        // stage V: 128 keys x 16 float4 -> [key][72]
        const float4* vg = (const float4*)(g_v + ((size_t)b * N_ + kstart) * C_);
#pragma unroll
        for (int i = tid; i < NK * 16; i += 128) {
            const int key = i >> 4, c4 = i & 15;
            *(float4*)(svt + key * VSTRIDE + c4 * 4) = vg[i];
        }
        __syncthreads();

#pragma unroll 4
        for (int s = 0; s < NK / 8; s++) {
            const int k0 = s * 8;
            // two key vectors this thread owns: kc0 = k0+cq, kc1 = kc0+4
            const float4 kA0 = skt[(k0 + cq) * 2],     kA1 = skt[(k0 + cq) * 2 + 1];
            const float4 kB0 = skt[(k0 + cq + 4) * 2], kB1 = skt[(k0 + cq + 4) * 2 + 1];
            const unsigned long long kAp[4] = { pack2(kA0.x, kA0.y), pack2(kA0.z, kA0.w),
                                                pack2(kA1.x, kA1.y), pack2(kA1.z, kA1.w) };
            const unsigned long long kBp[4] = { pack2(kB0.x, kB0.y), pack2(kB0.z, kB0.w),
                                                pack2(kB1.x, kB1.y), pack2(kB1.z, kB1.w) };

            unsigned long long e;
            e = mul2(qq0[3], kAp[3]); e = fma2(qq0[2], kAp[2], e);
            e = fma2(qq0[1], kAp[1], e); e = fma2(qq0[0], kAp[0], e);
            const float p00 = __expf(hadd2(e));
            e = mul2(qq1[3], kAp[3]); e = fma2(qq1[2], kAp[2], e);
            e = fma2(qq1[1], kAp[1], e); e = fma2(qq1[0], kAp[0], e);
            const float p10 = __expf(hadd2(e));
            e = mul2(qq0[3], kBp[3]); e = fma2(qq0[2], kBp[2], e);
            e = fma2(qq0[1], kBp[1], e); e = fma2(qq0[0], kBp[0], e);
            const float p01 = __expf(hadd2(e));
            e = mul2(qq1[3], kBp[3]); e = fma2(qq1[2], kBp[2], e);
            e = fma2(qq1[1], kBp[1], e); e = fma2(qq1[0], kBp[0], e);
            const float p11 = __expf(hadd2(e));

            den0 += p00 + p01;
            den1 += p10 + p11;

            const uint32_t a[4] = { f2tf32(p00), f2tf32(p10), f2tf32(p01), f2tf32(p11) };

            // B fragments: b0 = V[k0+cq][8j+grp], b1 = V[k0+cq+4][8j+grp]
            const float* vr0 = svt + (k0 + cq) * VSTRIDE + grp;
            const float* vr1 = vr0 + 4 * VSTRIDE;
#pragma unroll
            for (int j = 0; j < 8; j++) {
                mma_tf32(d[j], a, __float_as_uint(vr0[8 * j]), __float_as_uint(vr1[8 * j]));
            }
        }
    }

    // reduce den across the 4-lane key-class group
    den0 += __shfl_xor_sync(0xFFFFFFFFu, den0, 1);
    den0 += __shfl_xor_sync(0xFFFFFFFFu, den0, 2);
    den1 += __shfl_xor_sync(0xFFFFFFFFu, den1, 1);
    den1 += __shfl_xor_sync(0xFFFFFFFFu, den1, 2);

    // write partials: [B][S][q][64]
    float* p0 = g_pacc + (((size_t)(b * KS2 + sp) * N_) + q0g) * C_;
    float* p1 = g_pacc + (((size_t)(b * KS2 + sp) * N_) + q1g) * C_;
#pragma unroll
    for (int j = 0; j < 8; j++) {
        *(float2*)(p0 + 8 * j + 2 * cq) = make_float2(d[j][0], d[j][1]);
        *(float2*)(p1 + 8 * j + 2 * cq) = make_float2(d[j][2], d[j][3]);
    }
    if (cq == 0) {
        g_pden[(size_t)(b * KS2 + sp) * N_ + q0g] = den0;
        g_pden[(size_t)(b * KS2 + sp) * N_ + q1g] = den1;
    }
}

// ============================================================================
// Kernel 3: combine split partials + residual. thread = (b, n).
// ============================================================================
__global__ __launch_bounds__(128) void combine_kernel(
    const float* __restrict__ x,
    const float* __restrict__ gamma,
    float* __restrict__ out)
{
    const int t = blockIdx.x * 128 + threadIdx.x;   // 0..B*N-1
    const int b = t >> 12;
    const int n = t & (N_ - 1);

    const float den = g_pden[(size_t)(b * KS2) * N_ + n] + g_pden[(size_t)(b * KS2 + 1) * N_ + n];
    const float scale = gamma[0] / den;

    const float4* a0 = (const float4*)(g_pacc + (((size_t)(b * KS2 + 0) * N_) + n) * C_);
    const float4* a1 = (const float4*)(g_pacc + (((size_t)(b * KS2 + 1) * N_) + n) * C_);
#pragma unroll
    for (int c4 = 0; c4 < 16; c4++) {
        const float4 u = a0[c4], w = a1[c4];
        size_t o = ((size_t)b * C_ + c4 * 4) * N_ + n;
        out[o] = fmaf(scale, u.x + w.x, x[o]); o += N_;
        out[o] = fmaf(scale, u.y + w.y, x[o]); o += N_;
        out[o] = fmaf(scale, u.z + w.z, x[o]); o += N_;
        out[o] = fmaf(scale, u.w + w.w, x[o]);
    }
}

// ============================================================================
extern "C" void kernel_launch(void* const* d_in, const int* in_sizes, int n_in,
                              void* d_out, int out_size)
{
    const float* x     = (const float*)d_in[0];
    const float* Wq    = (const float*)d_in[1];
    const float* bq    = (const float*)d_in[2];
    const float* Wk    = (const float*)d_in[3];
    const float* bk    = (const float*)d_in[4];
    const float* Wv    = (const float*)d_in[5];
    const float* bv    = (const float*)d_in[6];
    const float* gamma = (const float*)d_in[7];
    float* out = (float*)d_out;

    qkv_kernel<<<(B_ * N_) / 32, 128>>>(x, Wq, bq, Wk, bk, Wv, bv);
    attn_mma_kernel<<<dim3(N_ / MT, KS2, B_), 128>>>();
    combine_kernel<<<(B_ * N_) / 128, 128>>>(x, gamma, out);
}

// round 6
// speedup vs baseline: 2.7224x; 1.2057x over previous
#include <cuda_runtime.h>
#include <cstdint>

// Shapes (fixed)
constexpr int B_   = 2;
constexpr int C_   = 64;
constexpr int CQK_ = 8;
constexpr int N_   = 4096;

constexpr int KS2 = 4;       // key splits
constexpr int MT  = 128;     // queries per CTA (8 warps x m16)
constexpr int NK  = 128;     // keys staged per tile
constexpr int VSTRIDE = 72;  // padded floats per key row in smem (conflict-free)

// ---------------- scratch ----------------
__device__ float g_q[B_ * N_ * CQK_];          // [B][N][8] (pre-scaled by log2e)
__device__ float g_k[B_ * N_ * CQK_];          // [B][N][8]
__device__ float g_v[B_ * N_ * C_];            // [B][N][64] key-major, tf32-rounded
__device__ float g_pacc[B_ * KS2 * N_ * C_];   // [B][S][q][64]
__device__ float g_pden[B_ * KS2 * N_];        // [B][S][q]

// ---------------- helpers ----------------
__device__ __forceinline__ unsigned long long fma2(unsigned long long a, unsigned long long b, unsigned long long c) {
    unsigned long long d;
    asm("fma.rn.f32x2 %0, %1, %2, %3;" : "=l"(d) : "l"(a), "l"(b), "l"(c));
    return d;
}
__device__ __forceinline__ unsigned long long mul2(unsigned long long a, unsigned long long b) {
    unsigned long long d;
    asm("mul.rn.f32x2 %0, %1, %2;" : "=l"(d) : "l"(a), "l"(b));
    return d;
}
__device__ __forceinline__ unsigned long long pack2(float lo, float hi) {
    unsigned long long r;
    asm("mov.b64 %0, {%1, %2};" : "=l"(r) : "f"(lo), "f"(hi));
    return r;
}
__device__ __forceinline__ float hadd2(unsigned long long a) {
    float lo, hi;
    asm("mov.b64 {%0, %1}, %2;" : "=f"(lo), "=f"(hi) : "l"(a));
    return lo + hi;
}
__device__ __forceinline__ float ex2f(float x) {
    float r;
    asm("ex2.approx.f32 %0, %1;" : "=f"(r) : "f"(x));
    return r;
}
__device__ __forceinline__ uint32_t f2tf32(float f) {
    uint32_t r;
    asm("cvt.rna.tf32.f32 %0, %1;" : "=r"(r) : "f"(f));
    return r;
}
// D[16x8] += A[16x8, tf32 row] * B[8x8, tf32 col]; accumulate in place
__device__ __forceinline__ void mma_tf32(float* d, const uint32_t* a, uint32_t b0, uint32_t b1) {
    asm volatile(
        "mma.sync.aligned.m16n8k8.row.col.f32.tf32.tf32.f32 "
        "{%0,%1,%2,%3}, {%4,%5,%6,%7}, {%8,%9}, {%0,%1,%2,%3};"
        : "+f"(d[0]), "+f"(d[1]), "+f"(d[2]), "+f"(d[3])
        : "r"(a[0]), "r"(a[1]), "r"(a[2]), "r"(a[3]), "r"(b0), "r"(b1));
}

// ============================================================================
// Kernel 1: QKV projection. Grid (256, 2) x 128 threads.
//  y=0: w0=q[0:8], w1=k[0:8], w2=v[0:8],  w3=v[8:16]
//  y=1: w0=v[16:28], w1=v[28:40], w2=v[40:52], w3=v[52:64]
// q is pre-scaled by log2(e) so attention can use raw ex2.
// V stored key-major [B][N][64], tf32-rounded.
// ============================================================================
__global__ __launch_bounds__(128) void qkv_kernel(
    const float* __restrict__ x,
    const float* __restrict__ Wq, const float* __restrict__ bq,
    const float* __restrict__ Wk, const float* __restrict__ bk,
    const float* __restrict__ Wv, const float* __restrict__ bv)
{
    __shared__ float swq[CQK_ * C_], swk[CQK_ * C_], swv[C_ * C_];
    __shared__ float sbq[CQK_], sbk[CQK_], sbv[C_];
    const int tid = threadIdx.x, wid = tid >> 5, lid = tid & 31;
    const int y = blockIdx.y;

    if (y == 0) {
        for (int i = tid; i < CQK_ * C_; i += 128) { swq[i] = Wq[i]; swk[i] = Wk[i]; }
        for (int i = tid; i < 16 * C_; i += 128) { swv[i] = Wv[i]; }
        if (tid < CQK_) { sbq[tid] = bq[tid]; sbk[tid] = bk[tid]; }
        if (tid < 16)   { sbv[tid] = bv[tid]; }
    } else {
        for (int i = tid; i < 48 * C_; i += 128) { swv[16 * C_ + i] = Wv[16 * C_ + i]; }
        if (tid < 48) { sbv[16 + tid] = bv[16 + tid]; }
    }
    __syncthreads();

    const int pos = blockIdx.x * 32 + lid;     // b*N + n
    const int b = pos >> 12;
    const int n = pos & (N_ - 1);

    float xr[C_];
    const float* xb = x + (size_t)b * C_ * N_ + n;
#pragma unroll
    for (int c = 0; c < C_; c++) xr[c] = xb[(size_t)c * N_];

    if (y == 0 && wid < 2) {
        const float* W  = wid ? swk : swq;
        const float* bb = wid ? sbk : sbq;
        const float scale = wid ? 1.0f : 1.44269504088896f;   // log2(e) into q
        float o[CQK_];
#pragma unroll
        for (int j = 0; j < CQK_; j++) {
            float a = bb[j];
#pragma unroll
            for (int c = 0; c < C_; c++) a += W[j * C_ + c] * xr[c];
            o[j] = a * scale;
        }
        float* dst = (wid ? g_k : g_q) + (size_t)pos * CQK_;
        ((float4*)dst)[0] = make_float4(o[0], o[1], o[2], o[3]);
        ((float4*)dst)[1] = make_float4(o[4], o[5], o[6], o[7]);
        return;
    }

    int c0, cnt;
    if (y == 0) { c0 = (wid - 2) * 8; cnt = 8; }       // v[0:8], v[8:16]
    else        { c0 = 16 + wid * 12; cnt = 12; }      // v[16:64] in 12s
    float* vo = g_v + (size_t)pos * C_;
    for (int jj = 0; jj < cnt; jj += 4) {
        float a0 = sbv[c0 + jj], a1 = sbv[c0 + jj + 1], a2 = sbv[c0 + jj + 2], a3 = sbv[c0 + jj + 3];
#pragma unroll
        for (int c = 0; c < C_; c++) {
            const float xv = xr[c];
            a0 += swv[(c0 + jj)     * C_ + c] * xv;
            a1 += swv[(c0 + jj + 1) * C_ + c] * xv;
            a2 += swv[(c0 + jj + 2) * C_ + c] * xv;
            a3 += swv[(c0 + jj + 3) * C_ + c] * xv;
        }
        *(float4*)(vo + c0 + jj) = make_float4(
            __uint_as_float(f2tf32(a0)), __uint_as_float(f2tf32(a1)),
            __uint_as_float(f2tf32(a2)), __uint_as_float(f2tf32(a3)));
    }
}

// ============================================================================
// Kernel 2: flash attention, PV on mma.sync tf32 (m16n8k8).
// Grid (N/MT=32, KS2=4, B=2), 256 threads = 8 warps; warp w owns queries
// [16w, 16w+16). Per NK=128 key tile: scalar QK^T + ex2 straight into A
// fragments, V (tf32) staged [key][72] as col-major B operand, 8 n-tiles mma.
// ============================================================================
__global__ __launch_bounds__(256, 2) void attn_mma_kernel()
{
    __shared__ float4 skt[NK * 2];                // K tile [128 keys][8]  (4 KB)
    __shared__ float  svt[NK * VSTRIDE];          // V tile [128 keys][72] (36 KB)

    const int tid = threadIdx.x, wid = tid >> 5, lane = tid & 31;
    const int b = blockIdx.z, sp = blockIdx.y, qt = blockIdx.x;
    const int grp = lane >> 2;        // 0..7
    const int cq  = lane & 3;         // 0..3

    const int q0g = qt * MT + wid * 16 + grp;     // r0
    const int q1g = q0g + 8;                      // r1

    const float4* qp0 = (const float4*)(g_q + ((size_t)b * N_ + q0g) * CQK_);
    const float4* qp1 = (const float4*)(g_q + ((size_t)b * N_ + q1g) * CQK_);
    const float4 qa0 = qp0[0], qa1 = qp0[1], qb0 = qp1[0], qb1 = qp1[1];
    const unsigned long long qq0[4] = { pack2(qa0.x, qa0.y), pack2(qa0.z, qa0.w),
                                        pack2(qa1.x, qa1.y), pack2(qa1.z, qa1.w) };
    const unsigned long long qq1[4] = { pack2(qb0.x, qb0.y), pack2(qb0.z, qb0.w),
                                        pack2(qb1.x, qb1.y), pack2(qb1.z, qb1.w) };

    float d[8][4];
#pragma unroll
    for (int j = 0; j < 8; j++) { d[j][0] = d[j][1] = d[j][2] = d[j][3] = 0.0f; }
    float den0 = 0.0f, den1 = 0.0f;

    const int kbase0 = sp * (N_ / KS2);
    for (int t = 0; t < (N_ / KS2) / NK; t++) {
        const int kstart = kbase0 + t * NK;
        __syncthreads();
        // stage K: 256 float4 over 256 threads
        const float4* kg = (const float4*)(g_k + ((size_t)b * N_ + kstart) * CQK_);
        skt[tid] = kg[tid];
        // stage V: 2048 float4 -> [key][72]
        const float4* vg = (const float4*)(g_v + ((size_t)b * N_ + kstart) * C_);
#pragma unroll
        for (int i = tid; i < NK * 16; i += 256) {
            const int key = i >> 4, c4 = i & 15;
            *(float4*)(svt + key * VSTRIDE + c4 * 4) = vg[i];
        }
        __syncthreads();

#pragma unroll 4
        for (int s = 0; s < NK / 8; s++) {
            const int k0 = s * 8;
            const float4 kA0 = skt[(k0 + cq) * 2],     kA1 = skt[(k0 + cq) * 2 + 1];
            const float4 kB0 = skt[(k0 + cq + 4) * 2], kB1 = skt[(k0 + cq + 4) * 2 + 1];
            const unsigned long long kAp[4] = { pack2(kA0.x, kA0.y), pack2(kA0.z, kA0.w),
                                                pack2(kA1.x, kA1.y), pack2(kA1.z, kA1.w) };
            const unsigned long long kBp[4] = { pack2(kB0.x, kB0.y), pack2(kB0.z, kB0.w),
                                                pack2(kB1.x, kB1.y), pack2(kB1.z, kB1.w) };

            unsigned long long e;
            e = mul2(qq0[3], kAp[3]); e = fma2(qq0[2], kAp[2], e);
            e = fma2(qq0[1], kAp[1], e); e = fma2(qq0[0], kAp[0], e);
            const float p00 = ex2f(hadd2(e));
            e = mul2(qq1[3], kAp[3]); e = fma2(qq1[2], kAp[2], e);
            e = fma2(qq1[1], kAp[1], e); e = fma2(qq1[0], kAp[0], e);
            const float p10 = ex2f(hadd2(e));
            e = mul2(qq0[3], kBp[3]); e = fma2(qq0[2], kBp[2], e);
            e = fma2(qq0[1], kBp[1], e); e = fma2(qq0[0], kBp[0], e);
            const float p01 = ex2f(hadd2(e));
            e = mul2(qq1[3], kBp[3]); e = fma2(qq1[2], kBp[2], e);
            e = fma2(qq1[1], kBp[1], e); e = fma2(qq1[0], kBp[0], e);
            const float p11 = ex2f(hadd2(e));

            den0 += p00 + p01;
            den1 += p10 + p11;

            const uint32_t a[4] = { f2tf32(p00), f2tf32(p10), f2tf32(p01), f2tf32(p11) };

            const float* vr0 = svt + (k0 + cq) * VSTRIDE + grp;
            const float* vr1 = vr0 + 4 * VSTRIDE;
#pragma unroll
            for (int j = 0; j < 8; j++) {
                mma_tf32(d[j], a, __float_as_uint(vr0[8 * j]), __float_as_uint(vr1[8 * j]));
            }
        }
    }

    den0 += __shfl_xor_sync(0xFFFFFFFFu, den0, 1);
    den0 += __shfl_xor_sync(0xFFFFFFFFu, den0, 2);
    den1 += __shfl_xor_sync(0xFFFFFFFFu, den1, 1);
    den1 += __shfl_xor_sync(0xFFFFFFFFu, den1, 2);

    float* p0 = g_pacc + (((size_t)(b * KS2 + sp) * N_) + q0g) * C_;
    float* p1 = g_pacc + (((size_t)(b * KS2 + sp) * N_) + q1g) * C_;
#pragma unroll
    for (int j = 0; j < 8; j++) {
        *(float2*)(p0 + 8 * j + 2 * cq) = make_float2(d[j][0], d[j][1]);
        *(float2*)(p1 + 8 * j + 2 * cq) = make_float2(d[j][2], d[j][3]);
    }
    if (cq == 0) {
        g_pden[(size_t)(b * KS2 + sp) * N_ + q0g] = den0;
        g_pden[(size_t)(b * KS2 + sp) * N_ + q1g] = den1;
    }
}

// ============================================================================
// Kernel 3: combine KS2 split partials + residual. thread = (b, n).
// ============================================================================
__global__ __launch_bounds__(128) void combine_kernel(
    const float* __restrict__ x,
    const float* __restrict__ gamma,
    float* __restrict__ out)
{
    const int t = blockIdx.x * 128 + threadIdx.x;   // 0..B*N-1
    const int b = t >> 12;
    const int n = t & (N_ - 1);

    float den = 0.0f;
#pragma unroll
    for (int s = 0; s < KS2; s++) den += g_pden[(size_t)(b * KS2 + s) * N_ + n];
    const float scale = gamma[0] / den;

    const float4* ap[KS2];
#pragma unroll
    for (int s = 0; s < KS2; s++)
        ap[s] = (const float4*)(g_pacc + (((size_t)(b * KS2 + s) * N_) + n) * C_);

#pragma unroll
    for (int c4 = 0; c4 < 16; c4++) {
        float sx = 0.f, sy = 0.f, sz = 0.f, sw = 0.f;
#pragma unroll
        for (int s = 0; s < KS2; s++) {
            const float4 u = ap[s][c4];
            sx += u.x; sy += u.y; sz += u.z; sw += u.w;
        }
        size_t o = ((size_t)b * C_ + c4 * 4) * N_ + n;
        out[o] = fmaf(scale, sx, x[o]); o += N_;
        out[o] = fmaf(scale, sy, x[o]); o += N_;
        out[o] = fmaf(scale, sz, x[o]); o += N_;
        out[o] = fmaf(scale, sw, x[o]);
    }
}

// ============================================================================
extern "C" void kernel_launch(void* const* d_in, const int* in_sizes, int n_in,
                              void* d_out, int out_size)
{
    const float* x     = (const float*)d_in[0];
    const float* Wq    = (const float*)d_in[1];
    const float* bq    = (const float*)d_in[2];
    const float* Wk    = (const float*)d_in[3];
    const float* bk    = (const float*)d_in[4];
    const float* Wv    = (const float*)d_in[5];
    const float* bv    = (const float*)d_in[6];
    const float* gamma = (const float*)d_in[7];
    float* out = (float*)d_out;

    qkv_kernel<<<dim3((B_ * N_) / 32, 2), 128>>>(x, Wq, bq, Wk, bk, Wv, bv);
    attn_mma_kernel<<<dim3(N_ / MT, KS2, B_), 256>>>();
    combine_kernel<<<(B_ * N_) / 128, 128>>>(x, gamma, out);
}

// round 10
// speedup vs baseline: 2.7237x; 1.0004x over previous
#include <cuda_runtime.h>
#include <cstdint>

// Shapes (fixed)
constexpr int B_   = 2;
constexpr int C_   = 64;
constexpr int CQK_ = 8;
constexpr int N_   = 4096;

constexpr int KS2 = 8;       // key splits
constexpr int MT  = 128;     // queries per CTA (8 warps x m16)
constexpr int NK  = 128;     // keys staged per tile
constexpr int VSTRIDE = 72;  // padded floats per key row in smem (conflict-free)

// ---------------- scratch ----------------
__device__ float g_q[B_ * N_ * CQK_];          // [B][N][8] (pre-scaled by log2e)
__device__ float g_k[B_ * N_ * CQK_];          // [B][N][8]
__device__ float g_v[B_ * N_ * C_];            // [B][N][64] key-major, tf32-rounded
__device__ float g_pacc[B_ * KS2 * N_ * C_];   // [B][S][q][64]
__device__ float g_pden[B_ * KS2 * N_];        // [B][S][q]

// ---------------- helpers ----------------
__device__ __forceinline__ unsigned long long fma2(unsigned long long a, unsigned long long b, unsigned long long c) {
    unsigned long long d;
    asm("fma.rn.f32x2 %0, %1, %2, %3;" : "=l"(d) : "l"(a), "l"(b), "l"(c));
    return d;
}
__device__ __forceinline__ unsigned long long mul2(unsigned long long a, unsigned long long b) {
    unsigned long long d;
    asm("mul.rn.f32x2 %0, %1, %2;" : "=l"(d) : "l"(a), "l"(b));
    return d;
}
__device__ __forceinline__ unsigned long long pack2(float lo, float hi) {
    unsigned long long r;
    asm("mov.b64 %0, {%1, %2};" : "=l"(r) : "f"(lo), "f"(hi));
    return r;
}
__device__ __forceinline__ float hadd2(unsigned long long a) {
    float lo, hi;
    asm("mov.b64 {%0, %1}, %2;" : "=f"(lo), "=f"(hi) : "l"(a));
    return lo + hi;
}
__device__ __forceinline__ float ex2f(float x) {
    float r;
    asm("ex2.approx.f32 %0, %1;" : "=f"(r) : "f"(x));
    return r;
}
__device__ __forceinline__ uint32_t f2tf32(float f) {
    uint32_t r;
    asm("cvt.rna.tf32.f32 %0, %1;" : "=r"(r) : "f"(f));
    return r;
}
// D[16x8] += A[16x8, tf32 row] * B[8x8, tf32 col]; accumulate in place
__device__ __forceinline__ void mma_tf32(float* d, const uint32_t* a, uint32_t b0, uint32_t b1) {
    asm volatile(
        "mma.sync.aligned.m16n8k8.row.col.f32.tf32.tf32.f32 "
        "{%0,%1,%2,%3}, {%4,%5,%6,%7}, {%8,%9}, {%0,%1,%2,%3};"
        : "+f"(d[0]), "+f"(d[1]), "+f"(d[2]), "+f"(d[3])
        : "r"(a[0]), "r"(a[1]), "r"(a[2]), "r"(a[3]), "r"(b0), "r"(b1));
}

// ============================================================================
// Kernel 1: QKV projection. Grid (256, 2) x 128 threads.
//  y=0: w0=q[0:8], w1=k[0:8], w2=v[0:8],  w3=v[8:16]
//  y=1: w0=v[16:28], w1=v[28:40], w2=v[40:52], w3=v[52:64]
// q is pre-scaled by log2(e) so attention can use raw ex2.
// V stored key-major [B][N][64], tf32-rounded.
// ============================================================================
__global__ __launch_bounds__(128) void qkv_kernel(
    const float* __restrict__ x,
    const float* __restrict__ Wq, const float* __restrict__ bq,
    const float* __restrict__ Wk, const float* __restrict__ bk,
    const float* __restrict__ Wv, const float* __restrict__ bv)
{
    __shared__ float swq[CQK_ * C_], swk[CQK_ * C_], swv[C_ * C_];
    __shared__ float sbq[CQK_], sbk[CQK_], sbv[C_];
    const int tid = threadIdx.x, wid = tid >> 5, lid = tid & 31;
    const int y = blockIdx.y;

    if (y == 0) {
        for (int i = tid; i < CQK_ * C_; i += 128) { swq[i] = Wq[i]; swk[i] = Wk[i]; }
        for (int i = tid; i < 16 * C_; i += 128) { swv[i] = Wv[i]; }
        if (tid < CQK_) { sbq[tid] = bq[tid]; sbk[tid] = bk[tid]; }
        if (tid < 16)   { sbv[tid] = bv[tid]; }
    } else {
        for (int i = tid; i < 48 * C_; i += 128) { swv[16 * C_ + i] = Wv[16 * C_ + i]; }
        if (tid < 48) { sbv[16 + tid] = bv[16 + tid]; }
    }
    __syncthreads();

    const int pos = blockIdx.x * 32 + lid;     // b*N + n
    const int b = pos >> 12;
    const int n = pos & (N_ - 1);

    float xr[C_];
    const float* xb = x + (size_t)b * C_ * N_ + n;
#pragma unroll
    for (int c = 0; c < C_; c++) xr[c] = xb[(size_t)c * N_];

    if (y == 0 && wid < 2) {
        const float* W  = wid ? swk : swq;
        const float* bb = wid ? sbk : sbq;
        const float scale = wid ? 1.0f : 1.44269504088896f;   // log2(e) into q
        float o[CQK_];
#pragma unroll
        for (int j = 0; j < CQK_; j++) {
            float a = bb[j];
#pragma unroll
            for (int c = 0; c < C_; c++) a += W[j * C_ + c] * xr[c];
            o[j] = a * scale;
        }
        float* dst = (wid ? g_k : g_q) + (size_t)pos * CQK_;
        ((float4*)dst)[0] = make_float4(o[0], o[1], o[2], o[3]);
        ((float4*)dst)[1] = make_float4(o[4], o[5], o[6], o[7]);
        return;
    }

    int c0, cnt;
    if (y == 0) { c0 = (wid - 2) * 8; cnt = 8; }       // v[0:8], v[8:16]
    else        { c0 = 16 + wid * 12; cnt = 12; }      // v[16:64] in 12s
    float* vo = g_v + (size_t)pos * C_;
    for (int jj = 0; jj < cnt; jj += 4) {
        float a0 = sbv[c0 + jj], a1 = sbv[c0 + jj + 1], a2 = sbv[c0 + jj + 2], a3 = sbv[c0 + jj + 3];
#pragma unroll
        for (int c = 0; c < C_; c++) {
            const float xv = xr[c];
            a0 += swv[(c0 + jj)     * C_ + c] * xv;
            a1 += swv[(c0 + jj + 1) * C_ + c] * xv;
            a2 += swv[(c0 + jj + 2) * C_ + c] * xv;
            a3 += swv[(c0 + jj + 3) * C_ + c] * xv;
        }
        *(float4*)(vo + c0 + jj) = make_float4(
            __uint_as_float(f2tf32(a0)), __uint_as_float(f2tf32(a1)),
            __uint_as_float(f2tf32(a2)), __uint_as_float(f2tf32(a3)));
    }
}

// ============================================================================
// Kernel 2: flash attention, PV on mma.sync tf32 (m16n8k8).
// Grid (N/MT=32, KS2=8, B=2), 256 threads = 8 warps; warp w owns queries
// [16w, 16w+16). Per NK=128 key tile: scalar QK^T + ex2 straight into A
// fragments, V (tf32) staged [key][72] as col-major B operand, 8 n-tiles mma.
// ============================================================================
__global__ __launch_bounds__(256, 2) void attn_mma_kernel()
{
    __shared__ float4 skt[NK * 2];                // K tile [128 keys][8]  (4 KB)
    __shared__ float  svt[NK * VSTRIDE];          // V tile [128 keys][72] (36 KB)

    const int tid = threadIdx.x, wid = tid >> 5, lane = tid & 31;
    const int b = blockIdx.z, sp = blockIdx.y, qt = blockIdx.x;
    const int grp = lane >> 2;        // 0..7
    const int cq  = lane & 3;         // 0..3

    const int q0g = qt * MT + wid * 16 + grp;     // r0
    const int q1g = q0g + 8;                      // r1

    const float4* qp0 = (const float4*)(g_q + ((size_t)b * N_ + q0g) * CQK_);
    const float4* qp1 = (const float4*)(g_q + ((size_t)b * N_ + q1g) * CQK_);
    const float4 qa0 = qp0[0], qa1 = qp0[1], qb0 = qp1[0], qb1 = qp1[1];
    const unsigned long long qq0[4] = { pack2(qa0.x, qa0.y), pack2(qa0.z, qa0.w),
                                        pack2(qa1.x, qa1.y), pack2(qa1.z, qa1.w) };
    const unsigned long long qq1[4] = { pack2(qb0.x, qb0.y), pack2(qb0.z, qb0.w),
                                        pack2(qb1.x, qb1.y), pack2(qb1.z, qb1.w) };

    float d[8][4];
#pragma unroll
    for (int j = 0; j < 8; j++) { d[j][0] = d[j][1] = d[j][2] = d[j][3] = 0.0f; }
    float den0 = 0.0f, den1 = 0.0f;

    const int kbase0 = sp * (N_ / KS2);
    for (int t = 0; t < (N_ / KS2) / NK; t++) {
        const int kstart = kbase0 + t * NK;
        __syncthreads();
        // stage K: 256 float4 over 256 threads
        const float4* kg = (const float4*)(g_k + ((size_t)b * N_ + kstart) * CQK_);
        skt[tid] = kg[tid];
        // stage V: 2048 float4 -> [key][72]
        const float4* vg = (const float4*)(g_v + ((size_t)b * N_ + kstart) * C_);
#pragma unroll
        for (int i = tid; i < NK * 16; i += 256) {
            const int key = i >> 4, c4 = i & 15;
            *(float4*)(svt + key * VSTRIDE + c4 * 4) = vg[i];
        }
        __syncthreads();

#pragma unroll 4
        for (int s = 0; s < NK / 8; s++) {
            const int k0 = s * 8;
            const float4 kA0 = skt[(k0 + cq) * 2],     kA1 = skt[(k0 + cq) * 2 + 1];
            const float4 kB0 = skt[(k0 + cq + 4) * 2], kB1 = skt[(k0 + cq + 4) * 2 + 1];
            const unsigned long long kAp[4] = { pack2(kA0.x, kA0.y), pack2(kA0.z, kA0.w),
                                                pack2(kA1.x, kA1.y), pack2(kA1.z, kA1.w) };
            const unsigned long long kBp[4] = { pack2(kB0.x, kB0.y), pack2(kB0.z, kB0.w),
                                                pack2(kB1.x, kB1.y), pack2(kB1.z, kB1.w) };

            unsigned long long e;
            e = mul2(qq0[3], kAp[3]); e = fma2(qq0[2], kAp[2], e);
            e = fma2(qq0[1], kAp[1], e); e = fma2(qq0[0], kAp[0], e);
            const float p00 = ex2f(hadd2(e));
            e = mul2(qq1[3], kAp[3]); e = fma2(qq1[2], kAp[2], e);
            e = fma2(qq1[1], kAp[1], e); e = fma2(qq1[0], kAp[0], e);
            const float p10 = ex2f(hadd2(e));
            e = mul2(qq0[3], kBp[3]); e = fma2(qq0[2], kBp[2], e);
            e = fma2(qq0[1], kBp[1], e); e = fma2(qq0[0], kBp[0], e);
            const float p01 = ex2f(hadd2(e));
            e = mul2(qq1[3], kBp[3]); e = fma2(qq1[2], kBp[2], e);
            e = fma2(qq1[1], kBp[1], e); e = fma2(qq1[0], kBp[0], e);
            const float p11 = ex2f(hadd2(e));

            den0 += p00 + p01;
            den1 += p10 + p11;

            const uint32_t a[4] = { f2tf32(p00), f2tf32(p10), f2tf32(p01), f2tf32(p11) };

            const float* vr0 = svt + (k0 + cq) * VSTRIDE + grp;
            const float* vr1 = vr0 + 4 * VSTRIDE;
#pragma unroll
            for (int j = 0; j < 8; j++) {
                mma_tf32(d[j], a, __float_as_uint(vr0[8 * j]), __float_as_uint(vr1[8 * j]));
            }
        }
    }

    den0 += __shfl_xor_sync(0xFFFFFFFFu, den0, 1);
    den0 += __shfl_xor_sync(0xFFFFFFFFu, den0, 2);
    den1 += __shfl_xor_sync(0xFFFFFFFFu, den1, 1);
    den1 += __shfl_xor_sync(0xFFFFFFFFu, den1, 2);

    float* p0 = g_pacc + (((size_t)(b * KS2 + sp) * N_) + q0g) * C_;
    float* p1 = g_pacc + (((size_t)(b * KS2 + sp) * N_) + q1g) * C_;
#pragma unroll
    for (int j = 0; j < 8; j++) {
        *(float2*)(p0 + 8 * j + 2 * cq) = make_float2(d[j][0], d[j][1]);
        *(float2*)(p1 + 8 * j + 2 * cq) = make_float2(d[j][2], d[j][3]);
    }
    if (cq == 0) {
        g_pden[(size_t)(b * KS2 + sp) * N_ + q0g] = den0;
        g_pden[(size_t)(b * KS2 + sp) * N_ + q1g] = den1;
    }
}

// ============================================================================
// Kernel 3: combine KS2 split partials + residual.
// Grid (64, 4) x 128: thread = (b, n), blockIdx.y = channel quarter.
// ============================================================================
__global__ __launch_bounds__(128) void combine_kernel(
    const float* __restrict__ x,
    const float* __restrict__ gamma,
    float* __restrict__ out)
{
    const int t = blockIdx.x * 128 + threadIdx.x;   // 0..B*N-1
    const int b = t >> 12;
    const int n = t & (N_ - 1);
    const int c4base = blockIdx.y * 4;              // 4 c4-chunks per block row

    float den = 0.0f;
#pragma unroll
    for (int s = 0; s < KS2; s++) den += g_pden[(size_t)(b * KS2 + s) * N_ + n];
    const float scale = gamma[0] / den;

#pragma unroll
    for (int c4 = c4base; c4 < c4base + 4; c4++) {
        float sx = 0.f, sy = 0.f, sz = 0.f, sw = 0.f;
#pragma unroll
        for (int s = 0; s < KS2; s++) {
            const float4 u = ((const float4*)(g_pacc + (((size_t)(b * KS2 + s) * N_) + n) * C_))[c4];
            sx += u.x; sy += u.y; sz += u.z; sw += u.w;
        }
        size_t o = ((size_t)b * C_ + c4 * 4) * N_ + n;
        out[o] = fmaf(scale, sx, x[o]); o += N_;
        out[o] = fmaf(scale, sy, x[o]); o += N_;
        out[o] = fmaf(scale, sz, x[o]); o += N_;
        out[o] = fmaf(scale, sw, x[o]);
    }
}

// ============================================================================
extern "C" void kernel_launch(void* const* d_in, const int* in_sizes, int n_in,
                              void* d_out, int out_size)
{
    const float* x     = (const float*)d_in[0];
    const float* Wq    = (const float*)d_in[1];
    const float* bq    = (const float*)d_in[2];
    const float* Wk    = (const float*)d_in[3];
    const float* bk    = (const float*)d_in[4];
    const float* Wv    = (const float*)d_in[5];
    const float* bv    = (const float*)d_in[6];
    const float* gamma = (const float*)d_in[7];
    float* out = (float*)d_out;

    qkv_kernel<<<dim3((B_ * N_) / 32, 2), 128>>>(x, Wq, bq, Wk, bk, Wv, bv);
    attn_mma_kernel<<<dim3(N_ / MT, KS2, B_), 256>>>();
    combine_kernel<<<dim3((B_ * N_) / 128, 4), 128>>>(x, gamma, out);
}